// round 1
// baseline (speedup 1.0000x reference)
#include <cuda_runtime.h>

// ---------------------------------------------------------------------------
// QCNN on 13 qubits, B=2, collapsed to 23 two-qubit gates on the flat
// 8192-amplitude state + readout sum. One block per batch, state in smem.
// ---------------------------------------------------------------------------

#define NT 512
// smem layout (float2 units): c[8192], Us[64], sA[64], sT[64], sE[64], red[32 floats]
#define SMEM_BYTES (8448 * 8 + 128)

struct c2 { float x, y; };

__device__ __forceinline__ c2 cfma(c2 a, c2 b, c2 acc) {
    acc.x = fmaf(a.x, b.x, fmaf(-a.y, b.y, acc.x));
    acc.y = fmaf(a.x, b.y, fmaf( a.y, b.x, acc.y));
    return acc;
}

// Bank swizzle: fold i bits 4..7 into low 4 bits with GF(2) masks chosen so that
// every pass's 4 lowest free positions map to independent bank bits.
// bit4 -> 2, bit5 -> 5, bit6 -> 9, bit7 -> 2
__host__ __device__ constexpr unsigned foldbits(unsigned h) {
    return (((h & 1u) ^ ((h >> 3) & 1u)) ? 2u : 0u)
         ^ (((h >> 1) & 1u) ? 5u : 0u)
         ^ (((h >> 2) & 1u) ? 9u : 0u);
}
__device__ __forceinline__ unsigned swz(unsigned i) { return i ^ foldbits((i >> 4) & 15u); }

template <int P>
__device__ __forceinline__ unsigned ins(unsigned x) {
    return ((x & ~((1u << P) - 1u)) << 1) | (x & ((1u << P) - 1u));
}

// Load a 16-amplitude group: free bit positions P0<P1<P2<P3, group id = t (9 bits).
template <int P0, int P1, int P2, int P3>
__device__ __forceinline__ unsigned pass_load(const c2* __restrict__ c, unsigned t, c2 v[16]) {
    unsigned x = ins<P3>(ins<P2>(ins<P1>(ins<P0>(t))));
    unsigned sb = swz(x);
#pragma unroll
    for (int k = 0; k < 16; ++k) {
        unsigned off = ((k & 1) ? (1u << P0) : 0u) | ((k & 2) ? (1u << P1) : 0u) |
                       ((k & 4) ? (1u << P2) : 0u) | ((k & 8) ? (1u << P3) : 0u);
        unsigned so = off ^ foldbits((off >> 4) & 15u);   // compile-time constant
        v[k] = c[sb ^ so];
    }
    return sb;
}

template <int P0, int P1, int P2, int P3>
__device__ __forceinline__ void pass_store(c2* __restrict__ c, unsigned sb, const c2 v[16]) {
#pragma unroll
    for (int k = 0; k < 16; ++k) {
        unsigned off = ((k & 1) ? (1u << P0) : 0u) | ((k & 2) ? (1u << P1) : 0u) |
                       ((k & 4) ? (1u << P2) : 0u) | ((k & 8) ? (1u << P3) : 0u);
        unsigned so = off ^ foldbits((off >> 4) & 15u);
        c[sb ^ so] = v[k];
    }
}

__device__ __forceinline__ c2 lin4(const c2* __restrict__ u, c2 a0, c2 a1, c2 a2, c2 a3) {
    c2 acc; acc.x = 0.f; acc.y = 0.f;
    acc = cfma(u[0], a0, acc);
    acc = cfma(u[1], a1, acc);
    acc = cfma(u[2], a2, acc);
    acc = cfma(u[3], a3, acc);
    return acc;
}

// Apply 4x4 gate U to local bits LH (high bit of gate index) and LL (low bit).
template <int LH, int LL>
__device__ __forceinline__ void gate(c2 v[16], const c2* __restrict__ U) {
    constexpr int mH = 1 << LH, mL = 1 << LL;
#pragma unroll
    for (int r = 0; r < 16; ++r) {
        if (r & (mH | mL)) continue;
        c2 a0 = v[r], a1 = v[r | mL], a2 = v[r | mH], a3 = v[r | mH | mL];
        v[r]           = lin4(U + 0,  a0, a1, a2, a3);
        v[r | mL]      = lin4(U + 4,  a0, a1, a2, a3);
        v[r | mH]      = lin4(U + 8,  a0, a1, a2, a3);
        v[r | mH | mL] = lin4(U + 12, a0, a1, a2, a3);
    }
}

__global__ void __launch_bounds__(NT, 1)
qcnn_kernel(const float* __restrict__ pr, const float* __restrict__ pi,
            const float* __restrict__ Hr, const float* __restrict__ Hi,
            float* __restrict__ out)
{
    extern __shared__ c2 smem[];
    c2* c   = smem;          // 8192
    c2* Us  = smem + 8192;   // 64  (4 layers x 16)
    c2* sA  = smem + 8256;   // 64  expm scratch
    c2* sT  = smem + 8320;   // 64
    c2* sE  = smem + 8384;   // 64
    float* red = (float*)(smem + 8448);  // 32 floats

    const unsigned t = threadIdx.x;
    const unsigned b = blockIdx.x;
    const float* prb = pr + (b << 13);
    const float* pib = pi + (b << 13);

    // ---- load state (swizzled) + norm^2 partial ----
    float ns = 0.f;
#pragma unroll
    for (int it = 0; it < 16; ++it) {
        unsigned i = t + ((unsigned)it << 9);
        float re = prb[i], im = pib[i];
        c2 val; val.x = re; val.y = im;
        c[swz(i)] = val;
        ns = fmaf(re, re, fmaf(im, im, ns));
    }
#pragma unroll
    for (int o = 16; o; o >>= 1) ns += __shfl_xor_sync(0xffffffffu, ns, o);
    if ((t & 31u) == 0u) red[t >> 5] = ns;

    // ---- expm(H - H^dag) for 4 layers: warps 0,1; 16 lanes per layer ----
    if (t < 64u) {
        const int L = (int)(t >> 4);
        const int e = (int)(t & 15u);
        const int i = e >> 2, j = e & 3;
        const float* HrL = Hr + L * 16;
        const float* HiL = Hi + L * 16;
        float ar = HrL[e] - HrL[j * 4 + i];
        float ai = HiL[e] + HiL[j * 4 + i];
        float f2 = fmaf(ar, ar, ai * ai);
#pragma unroll
        for (int o = 8; o; o >>= 1) f2 += __shfl_xor_sync(0xffffffffu, f2, o);
        float fro = sqrtf(f2);
        int s = 0; float x = fro;
        while (x > 0.25f && s < 14) { x *= 0.5f; ++s; }
        float sc = ldexpf(1.f, -s);
        c2 as; as.x = ar * sc; as.y = ai * sc;
        sA[t] = as; sT[t] = as;
        c2 e0; e0.x = as.x + ((i == j) ? 1.f : 0.f); e0.y = as.y;
        sE[t] = e0;
        __syncwarp();
        // Taylor terms k = 2..12 (norm <= 0.25 -> far below fp32 eps)
        for (int k = 2; k <= 12; ++k) {
            c2 acc; acc.x = 0.f; acc.y = 0.f;
#pragma unroll
            for (int m = 0; m < 4; ++m) acc = cfma(sT[L * 16 + i * 4 + m], sA[L * 16 + m * 4 + j], acc);
            __syncwarp();
            float inv = 1.f / (float)k;
            c2 nt; nt.x = acc.x * inv; nt.y = acc.y * inv;
            sT[t] = nt;
            c2 ee = sE[t]; ee.x += nt.x; ee.y += nt.y; sE[t] = ee;
            __syncwarp();
        }
        // squarings (uniform 14 iters, predicated)
        for (int q = 0; q < 14; ++q) {
            c2 acc; acc.x = 0.f; acc.y = 0.f;
#pragma unroll
            for (int m = 0; m < 4; ++m) acc = cfma(sE[L * 16 + i * 4 + m], sE[L * 16 + m * 4 + j], acc);
            __syncwarp();
            if (q < s) sE[t] = acc;
            __syncwarp();
        }
        Us[t] = sE[t];
    }
    __syncthreads();

    const c2* U0 = Us;
    const c2* U1 = Us + 16;
    const c2* U2 = Us + 32;
    const c2* U3 = Us + 48;

    // Gate positions p = 12 - qubit. Passes preserve the reference gate order
    // for every overlapping pair of gates.

    { // Pass A bits {9,10,11,12}: L0 gates (12,11),(10,9),(11,10)
        c2 v[16]; unsigned sb = pass_load<9,10,11,12>(c, t, v);
        gate<3,2>(v, U0); gate<1,0>(v, U0); gate<2,1>(v, U0);
        pass_store<9,10,11,12>(c, sb, v);
    }
    __syncthreads();
    { // Pass B bits {5,6,7,8}: L0 (8,7),(6,5),(7,6)
        c2 v[16]; unsigned sb = pass_load<5,6,7,8>(c, t, v);
        gate<3,2>(v, U0); gate<1,0>(v, U0); gate<2,1>(v, U0);
        pass_store<5,6,7,8>(c, sb, v);
    }
    __syncthreads();
    { // Pass C bits {1,2,3,4}: L0 (4,3),(2,1),(3,2)
        c2 v[16]; unsigned sb = pass_load<1,2,3,4>(c, t, v);
        gate<3,2>(v, U0); gate<1,0>(v, U0); gate<2,1>(v, U0);
        pass_store<1,2,3,4>(c, sb, v);
    }
    __syncthreads();
    { // Pass D bits {0,1,4,5}: L0 (5,4),(1,0)
        c2 v[16]; unsigned sb = pass_load<0,1,4,5>(c, t, v);
        gate<3,2>(v, U0); gate<1,0>(v, U0);
        pass_store<0,1,4,5>(c, sb, v);
    }
    __syncthreads();
    { // Pass E bits {7,8,9,11}: L0 (9,8) then L1 (11,9)
        c2 v[16]; unsigned sb = pass_load<7,8,9,11>(c, t, v);
        gate<2,1>(v, U0); gate<3,2>(v, U1);
        pass_store<7,8,9,11>(c, sb, v);
    }
    __syncthreads();
    { // Pass F bits {1,3,5,7}: L1 (7,5),(3,1),(5,3)
        c2 v[16]; unsigned sb = pass_load<1,3,5,7>(c, t, v);
        gate<3,2>(v, U1); gate<1,0>(v, U1); gate<2,1>(v, U1);
        pass_store<1,3,5,7>(c, sb, v);
    }
    __syncthreads();
    { // Pass G bits {0,1,7,9}: L1 (9,7),(1,0)
        c2 v[16]; unsigned sb = pass_load<0,1,7,9>(c, t, v);
        gate<3,2>(v, U1); gate<1,0>(v, U1);
        pass_store<0,1,7,9>(c, sb, v);
    }
    __syncthreads();
    { // Pass H bits {0,1,5,9}: L2 (9,5),(1,0),(5,1),(0,9); L3 (5,0); readout
        c2 v[16]; (void)pass_load<0,1,5,9>(c, t, v);
        gate<3,2>(v, U2); gate<1,0>(v, U2); gate<2,1>(v, U2);
        gate<0,3>(v, U2);          // L2 gate (labels 3,0): high bit at pos0, low at pos9
        gate<2,0>(v, U3);          // L3 gate: high at pos5, low at pos0
        float ls = 0.f;
#pragma unroll
        for (int k = 0; k < 16; k += 2)   // kept bit (pos 0 = local bit 0) == 0
            ls = fmaf(v[k].x, v[k].x, fmaf(v[k].y, v[k].y, ls));
#pragma unroll
        for (int o = 16; o; o >>= 1) ls += __shfl_xor_sync(0xffffffffu, ls, o);
        if ((t & 31u) == 0u) red[16 + (t >> 5)] = ls;
    }
    __syncthreads();

    if (t == 0) {
        float n2 = 0.f, s = 0.f;
#pragma unroll
        for (int w = 0; w < 16; ++w) { n2 += red[w]; s += red[16 + w]; }
        out[b] = s / n2;
    }
}

extern "C" void kernel_launch(void* const* d_in, const int* in_sizes, int n_in,
                              void* d_out, int out_size) {
    (void)in_sizes; (void)n_in; (void)out_size;
    const float* pr = (const float*)d_in[0];
    const float* pi = (const float*)d_in[1];
    const float* Hr = (const float*)d_in[2];
    const float* Hi = (const float*)d_in[3];
    float* out = (float*)d_out;

    cudaFuncSetAttribute(qcnn_kernel, cudaFuncAttributeMaxDynamicSharedMemorySize, SMEM_BYTES);
    qcnn_kernel<<<2, NT, SMEM_BYTES>>>(pr, pi, Hr, Hi, out);
}

// round 2
// speedup vs baseline: 1.4479x; 1.4479x over previous
#include <cuda_runtime.h>

// ---------------------------------------------------------------------------
// QCNN on 13 qubits, B=2, collapsed to 23 two-qubit gates on the flat
// 8192-amplitude state + readout. 32 blocks (16 per batch), 3 phases with
// hand-rolled global barriers; per-phase state chunk (512 amps) in smem.
// ---------------------------------------------------------------------------

#define NBLK 32
#define NT   128

struct c2 { float x, y; };

// Persistent device state (zero-initialized; reset by last block each launch)
__device__ unsigned g_cnt[2];
__device__ unsigned g_flag[2];
__device__ unsigned g_done;
__device__ float    g_part_n[NBLK];
__device__ float    g_part_s[NBLK];
__device__ c2       g_scr[2][16384];

__device__ __forceinline__ c2 cmul_acc(c2 a, c2 b, c2 acc) {
    acc.x = fmaf(a.x, b.x, fmaf(-a.y, b.y, acc.x));
    acc.y = fmaf(a.x, b.y, fmaf( a.y, b.x, acc.y));
    return acc;
}

// Bank swizzle: fold bits 4,5 of the 9-bit local index into bits 0..3.
// h4 = 0b1111, h5 = 0b1010 — chosen so every gate's half-warp access window is
// conflict-free (verified by GF(2) independence for all 23 gates).
__device__ __forceinline__ unsigned swz(unsigned l) {
    unsigned f = ((l & 16u) ? 15u : 0u) ^ ((l & 32u) ? 10u : 0u);
    return l ^ f;
}

template <int P>
__device__ __forceinline__ unsigned ins(unsigned x) {
    return ((x & ~((1u << P) - 1u)) << 1) | (x & ((1u << P) - 1u));
}

__device__ __forceinline__ c2 lin4(const c2* __restrict__ u, c2 a0, c2 a1, c2 a2, c2 a3) {
    c2 acc; acc.x = 0.f; acc.y = 0.f;
    acc = cmul_acc(u[0], a0, acc);
    acc = cmul_acc(u[1], a1, acc);
    acc = cmul_acc(u[2], a2, acc);
    acc = cmul_acc(u[3], a3, acc);
    return acc;
}

// Apply 4x4 gate on local bit positions LH (high gate bit), LL (low gate bit).
// One r-group (4 amplitudes) per thread; caller syncs between gates.
template <int LH, int LL>
__device__ __forceinline__ void gate(c2* __restrict__ cs, const c2* __restrict__ U, unsigned t) {
    constexpr int A = (LH < LL) ? LH : LL;
    constexpr int B = (LH < LL) ? LL : LH;
    unsigned base = ins<B>(ins<A>(t));
    constexpr unsigned mH = 1u << LH, mL = 1u << LL;
    unsigned i0 = swz(base), i1 = swz(base | mL), i2 = swz(base | mH), i3 = swz(base | mH | mL);
    c2 a0 = cs[i0], a1 = cs[i1], a2 = cs[i2], a3 = cs[i3];
    cs[i0] = lin4(U + 0,  a0, a1, a2, a3);
    cs[i1] = lin4(U + 4,  a0, a1, a2, a3);
    cs[i2] = lin4(U + 8,  a0, a1, a2, a3);
    cs[i3] = lin4(U + 12, a0, a1, a2, a3);
}

// Global index maps: (block bits bb, 9-bit local l) -> 13-bit amplitude index.
// Phase 2 block bits at positions {0,2,4,6}; local bits -> {1,3,5,7,8..12}.
__device__ __forceinline__ unsigned map2(unsigned bb, unsigned l) {
    return ((l & 1u) << 1) | ((l & 2u) << 2) | ((l & 4u) << 3) | ((l & 8u) << 4)
         | ((l >> 4) << 8)
         | (bb & 1u) | ((bb & 2u) << 1) | ((bb & 4u) << 2) | ((bb & 8u) << 3);
}
// Phase 3 block bits at positions {8,10,11,12}; local bits -> {0..7, 9}.
__device__ __forceinline__ unsigned map3(unsigned bb, unsigned l) {
    return (l & 255u) | ((l & 256u) << 1) | ((bb & 1u) << 8) | ((bb >> 1) << 10);
}

// Global barrier (threadFenceReduction pattern). Counters reset at kernel end.
__device__ __forceinline__ void gbar(int k) {
    __threadfence();
    __syncthreads();
    if (threadIdx.x == 0) {
        if (atomicAdd(&g_cnt[k], 1u) == NBLK - 1u) {
            unsigned one = 1u;
            asm volatile("st.release.gpu.global.u32 [%0], %1;" :: "l"(g_flag + k), "r"(one) : "memory");
        }
        unsigned v;
        do {
            asm volatile("ld.acquire.gpu.global.u32 %0, [%1];" : "=r"(v) : "l"(g_flag + k) : "memory");
        } while (v == 0u);
    }
    __syncthreads();
}

__global__ void __launch_bounds__(NT, 1)
qcnn_kernel(const float* __restrict__ pr, const float* __restrict__ pi,
            const float* __restrict__ Hr, const float* __restrict__ Hi,
            float* __restrict__ out)
{
    __shared__ c2 cs[512];
    __shared__ c2 Us[64];
    __shared__ c2 sA[64], sT[64], sE[64];
    __shared__ float red[8];

    const unsigned t   = threadIdx.x;
    const unsigned blk = blockIdx.x;
    const unsigned b   = blk >> 4;    // batch
    const unsigned bb  = blk & 15u;   // 4 block bits

    // ---- threads 0..63: expm(H - H^dag) for all 4 layers (validated code);
    //      threads 64..127: load this block's 512 amps + norm^2 partial ----
    if (t < 64u) {
        const int L = (int)(t >> 4);
        const int e = (int)(t & 15u);
        const int i = e >> 2, j = e & 3;
        const float* HrL = Hr + L * 16;
        const float* HiL = Hi + L * 16;
        float ar = HrL[e] - HrL[j * 4 + i];
        float ai = HiL[e] + HiL[j * 4 + i];
        float f2 = fmaf(ar, ar, ai * ai);
#pragma unroll
        for (int o = 8; o; o >>= 1) f2 += __shfl_xor_sync(0xffffffffu, f2, o);
        float fro = sqrtf(f2);
        int s = 0; float x = fro;
        while (x > 0.25f && s < 14) { x *= 0.5f; ++s; }
        float sc = ldexpf(1.f, -s);
        c2 as; as.x = ar * sc; as.y = ai * sc;
        sA[t] = as; sT[t] = as;
        c2 e0; e0.x = as.x + ((i == j) ? 1.f : 0.f); e0.y = as.y;
        sE[t] = e0;
        __syncwarp();
        for (int k = 2; k <= 12; ++k) {
            c2 acc; acc.x = 0.f; acc.y = 0.f;
#pragma unroll
            for (int m = 0; m < 4; ++m) acc = cmul_acc(sT[L * 16 + i * 4 + m], sA[L * 16 + m * 4 + j], acc);
            __syncwarp();
            float inv = 1.f / (float)k;
            c2 nt; nt.x = acc.x * inv; nt.y = acc.y * inv;
            sT[t] = nt;
            c2 ee = sE[t]; ee.x += nt.x; ee.y += nt.y; sE[t] = ee;
            __syncwarp();
        }
        for (int q = 0; q < 14; ++q) {
            c2 acc; acc.x = 0.f; acc.y = 0.f;
#pragma unroll
            for (int m = 0; m < 4; ++m) acc = cmul_acc(sE[L * 16 + i * 4 + m], sE[L * 16 + m * 4 + j], acc);
            __syncwarp();
            if (q < s) sE[t] = acc;
            __syncwarp();
        }
        Us[t] = sE[t];
    } else {
        const unsigned q = t - 64u;
        const float* prb = pr + (b << 13);
        const float* pib = pi + (b << 13);
        float ns = 0.f;
#pragma unroll
        for (int k = 0; k < 8; ++k) {
            unsigned l  = q + ((unsigned)k << 6);
            unsigned gi = (bb << 9) | l;          // phase-1 block bits {9..12}
            float re = prb[gi], im = pib[gi];
            c2 v; v.x = re; v.y = im;
            cs[swz(l)] = v;
            ns = fmaf(re, re, fmaf(im, im, ns));
        }
#pragma unroll
        for (int o = 16; o; o >>= 1) ns += __shfl_xor_sync(0xffffffffu, ns, o);
        if ((t & 31u) == 0u) red[(t >> 5) - 2u] = ns;
    }
    __syncthreads();
    if (t == 0u) g_part_n[blk] = red[0] + red[1];

    const c2* U0 = Us;
    const c2* U1 = Us + 16;
    const c2* U2 = Us + 32;
    const c2* U3 = Us + 48;

    // ---- Phase 1: L0 gates inside positions {0..8} (local == global) ----
    gate<8,7>(cs, U0, t); __syncthreads();
    gate<6,5>(cs, U0, t); __syncthreads();
    gate<4,3>(cs, U0, t); __syncthreads();
    gate<2,1>(cs, U0, t); __syncthreads();
    gate<7,6>(cs, U0, t); __syncthreads();
    gate<5,4>(cs, U0, t); __syncthreads();
    gate<3,2>(cs, U0, t); __syncthreads();
    gate<1,0>(cs, U0, t); __syncthreads();

#pragma unroll
    for (int k = 0; k < 4; ++k) {
        unsigned l = t + ((unsigned)k << 7);
        g_scr[0][(b << 13) | (bb << 9) | l] = cs[swz(l)];
    }
    gbar(0);

    // ---- Phase 2: block bits {0,2,4,6}; local: pos1->0,3->1,5->2,7->3,8->4,9->5,10->6,11->7,12->8
#pragma unroll
    for (int k = 0; k < 4; ++k) {
        unsigned l = t + ((unsigned)k << 7);
        cs[swz(l)] = g_scr[0][(b << 13) | map2(bb, l)];
    }
    __syncthreads();
    gate<8,7>(cs, U0, t); __syncthreads();   // L0 (12,11)
    gate<6,5>(cs, U0, t); __syncthreads();   // L0 (10,9)
    gate<7,6>(cs, U0, t); __syncthreads();   // L0 (11,10)
    gate<5,4>(cs, U0, t); __syncthreads();   // L0 (9,8)
    gate<7,5>(cs, U1, t); __syncthreads();   // L1 (11,9)
    gate<3,2>(cs, U1, t); __syncthreads();   // L1 (7,5)
    gate<1,0>(cs, U1, t); __syncthreads();   // L1 (3,1)
    gate<5,3>(cs, U1, t); __syncthreads();   // L1 (9,7)
    gate<2,1>(cs, U1, t); __syncthreads();   // L1 (5,3)

#pragma unroll
    for (int k = 0; k < 4; ++k) {
        unsigned l = t + ((unsigned)k << 7);
        g_scr[1][(b << 13) | map2(bb, l)] = cs[swz(l)];
    }
    gbar(1);

    // ---- Phase 3: block bits {8,10,11,12}; local: pos0..7 -> 0..7, pos9 -> 8
#pragma unroll
    for (int k = 0; k < 4; ++k) {
        unsigned l = t + ((unsigned)k << 7);
        cs[swz(l)] = g_scr[1][(b << 13) | map3(bb, l)];
    }
    __syncthreads();
    gate<1,0>(cs, U1, t); __syncthreads();   // L1 (1,0)
    gate<8,5>(cs, U2, t); __syncthreads();   // L2 (9,5)
    gate<1,0>(cs, U2, t); __syncthreads();   // L2 (1,0)
    gate<5,1>(cs, U2, t); __syncthreads();   // L2 (5,1)
    gate<0,8>(cs, U2, t); __syncthreads();   // L2 (0,9): high bit at pos0, low at pos9
    gate<5,0>(cs, U3, t); __syncthreads();   // L3 (5,0)

    // ---- Readout: P(bit at position 0 == 0) partial for this block ----
    float ls = 0.f;
#pragma unroll
    for (int k = 0; k < 4; ++k) {
        unsigned l = t + ((unsigned)k << 7);
        if (!(l & 1u)) {
            c2 v = cs[swz(l)];
            ls = fmaf(v.x, v.x, fmaf(v.y, v.y, ls));
        }
    }
#pragma unroll
    for (int o = 16; o; o >>= 1) ls += __shfl_xor_sync(0xffffffffu, ls, o);
    if ((t & 31u) == 0u) red[4 + (t >> 5)] = ls;
    __syncthreads();

    if (t == 0u) {
        g_part_s[blk] = red[4] + red[5] + red[6] + red[7];
        __threadfence();
        if (atomicAdd(&g_done, 1u) == NBLK - 1u) {
            __threadfence();
            float n0 = 0.f, n1 = 0.f, s0 = 0.f, s1 = 0.f;
            for (int i = 0; i < 16; ++i)  { n0 += g_part_n[i]; s0 += g_part_s[i]; }
            for (int i = 16; i < 32; ++i) { n1 += g_part_n[i]; s1 += g_part_s[i]; }
            out[0] = s0 / n0;
            out[1] = s1 / n1;
            // reset persistent state for the next (replayed) launch
            g_cnt[0] = 0u; g_cnt[1] = 0u;
            g_flag[0] = 0u; g_flag[1] = 0u;
            g_done = 0u;
        }
    }
}

extern "C" void kernel_launch(void* const* d_in, const int* in_sizes, int n_in,
                              void* d_out, int out_size) {
    (void)in_sizes; (void)n_in; (void)out_size;
    const float* pr = (const float*)d_in[0];
    const float* pi = (const float*)d_in[1];
    const float* Hr = (const float*)d_in[2];
    const float* Hi = (const float*)d_in[3];
    float* out = (float*)d_out;
    qcnn_kernel<<<NBLK, NT>>>(pr, pi, Hr, Hi, out);
}

// round 3
// speedup vs baseline: 1.9412x; 1.3407x over previous
#include <cuda_runtime.h>
#include <cstdint>

// ---------------------------------------------------------------------------
// QCNN on 13 qubits, B=2 -> 23 two-qubit gates on the flat 8192-amp state.
// Grid 32 x 128; one 16-CTA cluster per batch. Two gate phases; the phase
// boundary exchange and the final reduction both go over DSMEM (no global
// barrier, no global scratch).
// ---------------------------------------------------------------------------

#define NT      128
#define NBLK    32
#define CLUSTER 16

struct c2 { float x, y; };

__device__ __forceinline__ c2 cmul_acc(c2 a, c2 b, c2 acc) {
    acc.x = fmaf(a.x, b.x, fmaf(-a.y, b.y, acc.x));
    acc.y = fmaf(a.x, b.y, fmaf( a.y, b.x, acc.y));
    return acc;
}

// Bank swizzle: fold bits 4,5 of the 9-bit local index into bits 0..3.
// f4 = 0b1101, f5 = 0b1011 — verified full-rank (conflict-free) for the
// half-warp access windows of all 23 gate patterns in both phases.
__device__ __forceinline__ unsigned swz(unsigned l) {
    unsigned f = ((l & 16u) ? 13u : 0u) ^ ((l & 32u) ? 11u : 0u);
    return l ^ f;
}

template <int P>
__device__ __forceinline__ unsigned ins(unsigned x) {
    return ((x & ~((1u << P) - 1u)) << 1) | (x & ((1u << P) - 1u));
}

__device__ __forceinline__ c2 lin4(const c2* __restrict__ u, c2 a0, c2 a1, c2 a2, c2 a3) {
    c2 acc; acc.x = 0.f; acc.y = 0.f;
    acc = cmul_acc(u[0], a0, acc);
    acc = cmul_acc(u[1], a1, acc);
    acc = cmul_acc(u[2], a2, acc);
    acc = cmul_acc(u[3], a3, acc);
    return acc;
}

// Apply 4x4 gate on local bit positions LH (high gate bit), LL (low gate bit).
// One r-group per thread (128 threads == 128 groups); caller syncs.
template <int LH, int LL>
__device__ __forceinline__ void gate(c2* __restrict__ cs, const c2* __restrict__ U, unsigned t) {
    constexpr int A = (LH < LL) ? LH : LL;
    constexpr int B = (LH < LL) ? LL : LH;
    unsigned base = ins<B>(ins<A>(t));
    constexpr unsigned mH = 1u << LH, mL = 1u << LL;
    unsigned i0 = swz(base), i1 = swz(base | mL), i2 = swz(base | mH), i3 = swz(base | mH | mL);
    c2 a0 = cs[i0], a1 = cs[i1], a2 = cs[i2], a3 = cs[i3];
    cs[i0] = lin4(U + 0,  a0, a1, a2, a3);
    cs[i1] = lin4(U + 4,  a0, a1, a2, a3);
    cs[i2] = lin4(U + 8,  a0, a1, a2, a3);
    cs[i3] = lin4(U + 12, a0, a1, a2, a3);
}

// Phase-B global index: local bits -> positions {0,1,5,7,8,9,10,11,12},
// block bits bb -> positions {2,3,4,6}.
__device__ __forceinline__ unsigned giB(unsigned bb, unsigned l) {
    return (l & 3u) | ((l & 4u) << 3) | ((l & 8u) << 4) | ((l >> 4) << 8)
         | ((bb & 7u) << 2) | ((bb & 8u) << 3);
}

__device__ __forceinline__ unsigned sm32(const void* p) {
    return (unsigned)__cvta_generic_to_shared(p);
}

__device__ __forceinline__ c2 dsld(unsigned addr, unsigned rank) {
    unsigned ra;
    asm("mapa.shared::cluster.u32 %0, %1, %2;" : "=r"(ra) : "r"(addr), "r"(rank));
    float x, y;
    asm volatile("ld.shared::cluster.v2.f32 {%0,%1}, [%2];" : "=f"(x), "=f"(y) : "r"(ra));
    c2 v; v.x = x; v.y = y; return v;
}

#define CLUSTER_SYNC() do { \
    asm volatile("barrier.cluster.arrive.aligned;" ::: "memory"); \
    asm volatile("barrier.cluster.wait.aligned;"   ::: "memory"); \
} while (0)

__global__ void __launch_bounds__(NT, 1)
qcnn_kernel(const float* __restrict__ pr, const float* __restrict__ pi,
            const float* __restrict__ Hr, const float* __restrict__ Hi,
            float* __restrict__ out)
{
    __shared__ c2 bufA[512];
    __shared__ c2 bufB[512];
    __shared__ c2 Us[64];
    __shared__ c2 sA[64], sT[64], sE[64];
    __shared__ float red[8];
    __shared__ float2 spart;

    const unsigned t   = threadIdx.x;
    const unsigned blk = blockIdx.x;
    const unsigned b   = blk >> 4;          // batch == cluster id
    unsigned rank;
    asm("mov.u32 %0, %%cluster_ctarank;" : "=r"(rank));
    const unsigned bb = rank;               // 4 chunk bits (phase A: positions 9..12)

    // ---- threads 0..63: expm(H - H^dag) for 4 layers; 64..127: load chunk ----
    if (t < 64u) {
        const int L = (int)(t >> 4);
        const int e = (int)(t & 15u);
        const int i = e >> 2, j = e & 3;
        const float* HrL = Hr + L * 16;
        const float* HiL = Hi + L * 16;
        float ar = HrL[e] - HrL[j * 4 + i];
        float ai = HiL[e] + HiL[j * 4 + i];
        float f2 = fmaf(ar, ar, ai * ai);
#pragma unroll
        for (int o = 8; o; o >>= 1) f2 += __shfl_xor_sync(0xffffffffu, f2, o);
        float fro = sqrtf(f2);
        int s = 0; float x = fro;
        while (x > 0.25f && s < 14) { x *= 0.5f; ++s; }
        float sc = ldexpf(1.f, -s);
        c2 as; as.x = ar * sc; as.y = ai * sc;
        sA[t] = as; sT[t] = as;
        c2 e0; e0.x = as.x + ((i == j) ? 1.f : 0.f); e0.y = as.y;
        sE[t] = e0;
        __syncwarp();
        // Taylor terms k = 2..9 (norm <= 0.25 -> term9 ~1e-11, below fp32 eps)
        for (int k = 2; k <= 9; ++k) {
            c2 acc; acc.x = 0.f; acc.y = 0.f;
#pragma unroll
            for (int m = 0; m < 4; ++m) acc = cmul_acc(sT[L * 16 + i * 4 + m], sA[L * 16 + m * 4 + j], acc);
            __syncwarp();
            float inv = 1.f / (float)k;
            c2 nt; nt.x = acc.x * inv; nt.y = acc.y * inv;
            sT[t] = nt;
            c2 ee = sE[t]; ee.x += nt.x; ee.y += nt.y; sE[t] = ee;
            __syncwarp();
        }
        // squarings: run warp-max(s) iterations, predicated writes
        int smax = s;
#pragma unroll
        for (int o = 16; o; o >>= 1) {
            int v = __shfl_xor_sync(0xffffffffu, smax, o);
            smax = v > smax ? v : smax;
        }
        for (int q = 0; q < smax; ++q) {
            c2 acc; acc.x = 0.f; acc.y = 0.f;
#pragma unroll
            for (int m = 0; m < 4; ++m) acc = cmul_acc(sE[L * 16 + i * 4 + m], sE[L * 16 + m * 4 + j], acc);
            __syncwarp();
            if (q < s) sE[t] = acc;
            __syncwarp();
        }
        Us[t] = sE[t];
    } else {
        const unsigned q = t - 64u;
        const float* prb = pr + (b << 13);
        const float* pib = pi + (b << 13);
        float ns = 0.f;
#pragma unroll
        for (int k = 0; k < 8; ++k) {
            unsigned l  = q + ((unsigned)k << 6);
            unsigned gi = (bb << 9) | l;        // phase-A block bits at 9..12
            float re = prb[gi], im = pib[gi];
            c2 v; v.x = re; v.y = im;
            bufA[swz(l)] = v;
            ns = fmaf(re, re, fmaf(im, im, ns));
        }
#pragma unroll
        for (int o = 16; o; o >>= 1) ns += __shfl_xor_sync(0xffffffffu, ns, o);
        if ((t & 31u) == 0u) red[(t >> 5) - 2u] = ns;
    }
    __syncthreads();
    const float n_part = red[0] + red[1];

    const c2* U0 = Us;
    const c2* U1 = Us + 16;
    const c2* U2 = Us + 32;
    const c2* U3 = Us + 48;

    // ---- Phase A: positions {0..8} local (identity map) ----
    gate<8,7>(bufA, U0, t); __syncthreads();   // L0 (8,7)
    gate<6,5>(bufA, U0, t); __syncthreads();   // L0 (6,5)
    gate<4,3>(bufA, U0, t); __syncthreads();   // L0 (4,3)
    gate<2,1>(bufA, U0, t); __syncthreads();   // L0 (2,1)
    gate<7,6>(bufA, U0, t); __syncthreads();   // L0 (7,6)
    gate<5,4>(bufA, U0, t); __syncthreads();   // L0 (5,4)
    gate<3,2>(bufA, U0, t); __syncthreads();   // L0 (3,2)
    gate<1,0>(bufA, U0, t); __syncthreads();   // L0 (1,0)
    gate<7,5>(bufA, U1, t); __syncthreads();   // L1 (7,5)
    gate<3,1>(bufA, U1, t); __syncthreads();   // L1 (3,1)
    gate<5,3>(bufA, U1, t); __syncthreads();   // L1 (5,3)
    gate<1,0>(bufA, U1, t); __syncthreads();   // L1 (1,0)

    // ---- Exchange: all peers' phase-A results visible after cluster sync ----
    CLUSTER_SYNC();
    {
        const unsigned bufA_a = sm32(bufA);
#pragma unroll
        for (int k = 0; k < 4; ++k) {
            unsigned l     = t + ((unsigned)k << 7);
            unsigned gi    = giB(bb, l);
            unsigned owner = gi >> 9;
            unsigned la    = gi & 511u;
            bufB[swz(l)]   = dsld(bufA_a + swz(la) * 8u, owner);
        }
    }
    __syncthreads();

    // ---- Phase B: local bits -> positions {0,1,5,7,8,9,10,11,12} ----
    gate<8,7>(bufB, U0, t); __syncthreads();   // L0 (12,11)
    gate<6,5>(bufB, U0, t); __syncthreads();   // L0 (10,9)
    gate<7,6>(bufB, U0, t); __syncthreads();   // L0 (11,10)
    gate<5,4>(bufB, U0, t); __syncthreads();   // L0 (9,8)
    gate<7,5>(bufB, U1, t); __syncthreads();   // L1 (11,9)
    gate<5,3>(bufB, U1, t); __syncthreads();   // L1 (9,7)
    gate<5,2>(bufB, U2, t); __syncthreads();   // L2 (9,5)
    gate<1,0>(bufB, U2, t); __syncthreads();   // L2 (1,0)
    gate<2,1>(bufB, U2, t); __syncthreads();   // L2 (5,1)
    gate<0,5>(bufB, U2, t); __syncthreads();   // L2 (0,9): high@pos0, low@pos9
    gate<2,0>(bufB, U3, t); __syncthreads();   // L3 (5,0)

    // ---- Readout partial: P(bit at position 0 == 0) over this chunk ----
    float ls = 0.f;
#pragma unroll
    for (int k = 0; k < 4; ++k) {
        unsigned l = t + ((unsigned)k << 7);
        if (!(l & 1u)) {
            c2 v = bufB[swz(l)];
            ls = fmaf(v.x, v.x, fmaf(v.y, v.y, ls));
        }
    }
#pragma unroll
    for (int o = 16; o; o >>= 1) ls += __shfl_xor_sync(0xffffffffu, ls, o);
    if ((t & 31u) == 0u) red[4 + (t >> 5)] = ls;
    __syncthreads();
    if (t == 0u) {
        float2 p; p.x = n_part; p.y = red[4] + red[5] + red[6] + red[7];
        spart = p;
    }

    // ---- Final reduction over DSMEM (deterministic fixed order) ----
    CLUSTER_SYNC();
    if (rank == 0u && t == 0u) {
        const unsigned pa = sm32(&spart);
        float n = 0.f, s = 0.f;
#pragma unroll
        for (unsigned r = 0; r < CLUSTER; ++r) {
            c2 p = dsld(pa, r);
            n += p.x; s += p.y;
        }
        out[b] = s / n;
    }
    CLUSTER_SYNC();   // keep peers' smem alive until rank 0 finished reading
}

extern "C" void kernel_launch(void* const* d_in, const int* in_sizes, int n_in,
                              void* d_out, int out_size) {
    (void)in_sizes; (void)n_in; (void)out_size;
    const float* pr = (const float*)d_in[0];
    const float* pi = (const float*)d_in[1];
    const float* Hr = (const float*)d_in[2];
    const float* Hi = (const float*)d_in[3];
    float* out = (float*)d_out;

    cudaFuncSetAttribute(qcnn_kernel, cudaFuncAttributeNonPortableClusterSizeAllowed, 1);

    cudaLaunchConfig_t cfg = {};
    cfg.gridDim  = dim3(NBLK, 1, 1);
    cfg.blockDim = dim3(NT, 1, 1);
    cfg.dynamicSmemBytes = 0;
    cfg.stream = 0;
    cudaLaunchAttribute attr[1];
    attr[0].id = cudaLaunchAttributeClusterDimension;
    attr[0].val.clusterDim.x = CLUSTER;
    attr[0].val.clusterDim.y = 1;
    attr[0].val.clusterDim.z = 1;
    cfg.attrs = attr;
    cfg.numAttrs = 1;

    cudaLaunchKernelEx(&cfg, qcnn_kernel, pr, pi, Hr, Hi, out);
}

// round 4
// speedup vs baseline: 2.3571x; 1.2143x over previous
#include <cuda_runtime.h>
#include <cstdint>

// ---------------------------------------------------------------------------
// QCNN on 13 qubits, B=2 -> 23 two-qubit gates on the flat 8192-amp state.
// Grid 32 x 256; one 16-CTA cluster per batch. Two gate phases; phase-boundary
// exchange + final reduction over DSMEM. Gates: 2 threads per r-group
// (rows 0,1 vs 2,3), packed f32x2 complex FMA, ping-pong smem buffers.
// ---------------------------------------------------------------------------

#define NT      256
#define NBLK    32
#define CLUSTER 16

typedef unsigned long long u64;
struct c2 { float x, y; };

#define FMA2(d,a,b,c) asm("fma.rn.f32x2 %0,%1,%2,%3;" : "=l"(d) : "l"(a), "l"(b), "l"(c))
#define MUL2(d,a,b)   asm("mul.rn.f32x2 %0,%1,%2;"    : "=l"(d) : "l"(a), "l"(b))

__device__ __forceinline__ u64 swap64(u64 a) {
    unsigned lo, hi;
    asm("mov.b64 {%0,%1}, %2;" : "=r"(lo), "=r"(hi) : "l"(a));
    u64 r;
    asm("mov.b64 %0, {%1,%2};" : "=l"(r) : "r"(hi), "r"(lo));
    return r;
}

// Bank swizzle (linear over GF(2)): fold bits 4,5 of the 9-bit local index
// into bits 0..3. f4=0b1101, f5=0b1011 — verified conflict-free for the
// half-warp windows of all 23 gate patterns (same as round 3).
__host__ __device__ constexpr unsigned cswz(unsigned l) {
    return l ^ (((l & 16u) ? 13u : 0u) ^ ((l & 32u) ? 11u : 0u));
}

template <int P>
__device__ __forceinline__ unsigned ins(unsigned x) {
    return ((x & ~((1u << P) - 1u)) << 1) | (x & ((1u << P) - 1u));
}

__device__ __forceinline__ void loadPQ(const ulonglong2* __restrict__ PQv, int L,
                                       unsigned r0, ulonglong2 R0[4], ulonglong2 R1[4]) {
#pragma unroll
    for (int k = 0; k < 4; ++k) {
        R0[k] = PQv[L * 16 + (int)r0 * 4 + k];
        R1[k] = PQv[L * 16 + (int)(r0 + 1u) * 4 + k];
    }
}

// Gate on local bit positions LH (high gate bit), LL (low gate bit).
// Thread handles r-group g, rows {2h, 2h+1} (PQ rows preloaded in R0,R1).
// Reads src, writes dst (ping-pong) — no intra-gate race.
template <int LH, int LL>
__device__ __forceinline__ void gateP(const u64* __restrict__ src, u64* __restrict__ dst,
                                      const ulonglong2 R0[4], const ulonglong2 R1[4],
                                      unsigned g, unsigned h) {
    constexpr int A = (LH < LL) ? LH : LL;
    constexpr int B = (LH < LL) ? LL : LH;
    constexpr unsigned mH = 1u << LH, mL = 1u << LL;
    constexpr unsigned s1 = cswz(mL) ^ 0u;       // swz images of offsets
    constexpr unsigned s2 = cswz(mH) ^ 0u;
    constexpr unsigned s3 = cswz(mH | mL) ^ 0u;
    unsigned base = ins<B>(ins<A>(g));
    unsigned sb = cswz(base);
    u64 a0 = src[sb], a1 = src[sb ^ s1], a2 = src[sb ^ s2], a3 = src[sb ^ s3];
    u64 w0 = swap64(a0), w1 = swap64(a1), w2 = swap64(a2), w3 = swap64(a3);
    u64 acc0, acc1;
    MUL2(acc0, R0[0].x, a0); FMA2(acc0, R0[0].y, w0, acc0);
    FMA2(acc0, R0[1].x, a1, acc0); FMA2(acc0, R0[1].y, w1, acc0);
    FMA2(acc0, R0[2].x, a2, acc0); FMA2(acc0, R0[2].y, w2, acc0);
    FMA2(acc0, R0[3].x, a3, acc0); FMA2(acc0, R0[3].y, w3, acc0);
    MUL2(acc1, R1[0].x, a0); FMA2(acc1, R1[0].y, w0, acc1);
    FMA2(acc1, R1[1].x, a1, acc1); FMA2(acc1, R1[1].y, w1, acc1);
    FMA2(acc1, R1[2].x, a2, acc1); FMA2(acc1, R1[2].y, w2, acc1);
    FMA2(acc1, R1[3].x, a3, acc1); FMA2(acc1, R1[3].y, w3, acc1);
    unsigned o0 = h ? s2 : 0u;    // row 2h
    unsigned o1 = h ? s3 : s1;    // row 2h+1
    dst[sb ^ o0] = acc0;
    dst[sb ^ o1] = acc1;
}

// Phase-B global index: local bits -> positions {0,1,5,7,8,9,10,11,12},
// block bits bb -> positions {2,3,4,6}.
__device__ __forceinline__ unsigned giB(unsigned bb, unsigned l) {
    return (l & 3u) | ((l & 4u) << 3) | ((l & 8u) << 4) | ((l >> 4) << 8)
         | ((bb & 7u) << 2) | ((bb & 8u) << 3);
}

__device__ __forceinline__ unsigned sm32(const void* p) {
    return (unsigned)__cvta_generic_to_shared(p);
}

__device__ __forceinline__ c2 dsld(unsigned addr, unsigned rank) {
    unsigned ra;
    asm("mapa.shared::cluster.u32 %0, %1, %2;" : "=r"(ra) : "r"(addr), "r"(rank));
    float x, y;
    asm volatile("ld.shared::cluster.v2.f32 {%0,%1}, [%2];" : "=f"(x), "=f"(y) : "r"(ra));
    c2 v; v.x = x; v.y = y; return v;
}

#define CLUSTER_SYNC() do { \
    asm volatile("barrier.cluster.arrive.aligned;" ::: "memory"); \
    asm volatile("barrier.cluster.wait.aligned;"   ::: "memory"); \
} while (0)

__global__ void __launch_bounds__(NT, 1)
qcnn_kernel(const float* __restrict__ pr, const float* __restrict__ pi,
            const float* __restrict__ Hr, const float* __restrict__ Hi,
            float* __restrict__ out)
{
    __shared__ c2 bufA[512];
    __shared__ c2 bufB[512];
    __shared__ c2 bufC[512];
    __shared__ float4 Us4[64];      // PQ table: (u.x, u.x, -u.y, u.y) per entry
    __shared__ float red[8];
    __shared__ float2 spart;

    const unsigned t = threadIdx.x;
    const unsigned b = blockIdx.x >> 4;     // batch == cluster id
    unsigned rank;
    asm("mov.u32 %0, %%cluster_ctarank;" : "=r"(rank));
    const unsigned bb = rank;               // phase-A block bits (positions 9..12)

    u64* A64 = reinterpret_cast<u64*>(bufA);
    u64* B64 = reinterpret_cast<u64*>(bufB);
    u64* C64 = reinterpret_cast<u64*>(bufC);
    const ulonglong2* PQv = reinterpret_cast<const ulonglong2*>(Us4);

    // ---- threads 0..63: shfl-based expm(H - H^dag) for 4 layers;
    //      threads 128..255: load the chunk + norm^2 partial ----
    if (t < 64u) {
        const int L = (int)(t >> 4);
        const int e = (int)(t & 15u);
        const int i = e >> 2, j = e & 3;
        const unsigned lane = t & 31u;
        const unsigned seg  = lane & 16u;   // 16-lane segment base within warp
        const float* HrL = Hr + L * 16;
        const float* HiL = Hi + L * 16;
        float ar = HrL[e] - HrL[j * 4 + i];
        float ai = HiL[e] + HiL[j * 4 + i];
        float f2 = fmaf(ar, ar, ai * ai);
#pragma unroll
        for (int o = 8; o; o >>= 1) f2 += __shfl_xor_sync(0xffffffffu, f2, o);
        float fro = sqrtf(f2);
        int s = 0; float x = fro;
        while (x > 0.25f && s < 14) { x *= 0.5f; ++s; }
        float sc = ldexpf(1.f, -s);
        float Ar = ar * sc, Ai = ai * sc;
        float Tr = Ar, Ti = Ai;
        float Er = Ar + ((i == j) ? 1.f : 0.f), Ei = Ai;
        // Taylor terms k = 2..9 (norm <= 0.25)
#pragma unroll 1
        for (int k = 2; k <= 9; ++k) {
            float accr = 0.f, acci = 0.f;
#pragma unroll
            for (int m = 0; m < 4; ++m) {
                unsigned sT = seg | (unsigned)(i * 4 + m);
                unsigned sA = seg | (unsigned)(m * 4 + j);
                float tr = __shfl_sync(0xffffffffu, Tr, sT);
                float ti = __shfl_sync(0xffffffffu, Ti, sT);
                float br = __shfl_sync(0xffffffffu, Ar, sA);
                float bi = __shfl_sync(0xffffffffu, Ai, sA);
                accr = fmaf(tr, br, fmaf(-ti, bi, accr));
                acci = fmaf(tr, bi, fmaf( ti, br, acci));
            }
            float inv = 1.f / (float)k;
            Tr = accr * inv; Ti = acci * inv;
            Er += Tr; Ei += Ti;
        }
        // squarings: warp-max iterations, segment-uniform predicated commit
        int smax = s;
#pragma unroll
        for (int o = 16; o; o >>= 1) {
            int v = __shfl_xor_sync(0xffffffffu, smax, o);
            smax = v > smax ? v : smax;
        }
#pragma unroll 1
        for (int q = 0; q < smax; ++q) {
            float accr = 0.f, acci = 0.f;
#pragma unroll
            for (int m = 0; m < 4; ++m) {
                unsigned sR = seg | (unsigned)(i * 4 + m);
                unsigned sC = seg | (unsigned)(m * 4 + j);
                float rr = __shfl_sync(0xffffffffu, Er, sR);
                float ri = __shfl_sync(0xffffffffu, Ei, sR);
                float cr = __shfl_sync(0xffffffffu, Er, sC);
                float ci = __shfl_sync(0xffffffffu, Ei, sC);
                accr = fmaf(rr, cr, fmaf(-ri, ci, accr));
                acci = fmaf(rr, ci, fmaf( ri, cr, acci));
            }
            if (q < s) { Er = accr; Ei = acci; }
        }
        Us4[t] = make_float4(Er, Er, -Ei, Ei);
    } else if (t >= 128u) {
        const unsigned q = t - 128u;
        const float* prb = pr + (b << 13);
        const float* pib = pi + (b << 13);
        float4 r4 = *reinterpret_cast<const float4*>(prb + 4u * q + ((unsigned)bb << 9));
        float4 i4 = *reinterpret_cast<const float4*>(pib + 4u * q + ((unsigned)bb << 9));
        unsigned l0 = 4u * q;
        c2 v;
        v.x = r4.x; v.y = i4.x; bufA[cswz(l0 + 0u)] = v;
        v.x = r4.y; v.y = i4.y; bufA[cswz(l0 + 1u)] = v;
        v.x = r4.z; v.y = i4.z; bufA[cswz(l0 + 2u)] = v;
        v.x = r4.w; v.y = i4.w; bufA[cswz(l0 + 3u)] = v;
        float ns = fmaf(r4.x, r4.x, fmaf(i4.x, i4.x,
                   fmaf(r4.y, r4.y, fmaf(i4.y, i4.y,
                   fmaf(r4.z, r4.z, fmaf(i4.z, i4.z,
                   fmaf(r4.w, r4.w, i4.w * i4.w)))))));
#pragma unroll
        for (int o = 16; o; o >>= 1) ns += __shfl_xor_sync(0xffffffffu, ns, o);
        if ((t & 31u) == 0u) red[(t >> 5) - 4u] = ns;
    }
    __syncthreads();
    const float n_part = red[0] + red[1] + red[2] + red[3];

    const unsigned g = t & 127u;      // r-group id
    const unsigned h = t >> 7;        // row half: warps 0-3 rows{0,1}, 4-7 rows{2,3}
    const unsigned r0 = h * 2u;
    ulonglong2 R0[4], R1[4];

    // ---- Phase A: positions {0..8} local (identity map); block bits 9..12 ----
    loadPQ(PQv, 0, r0, R0, R1);
    gateP<8,7>(A64, B64, R0, R1, g, h); __syncthreads();   // L0 (8,7)
    gateP<6,5>(B64, A64, R0, R1, g, h); __syncthreads();   // L0 (6,5)
    gateP<4,3>(A64, B64, R0, R1, g, h); __syncthreads();   // L0 (4,3)
    gateP<2,1>(B64, A64, R0, R1, g, h); __syncthreads();   // L0 (2,1)
    gateP<7,6>(A64, B64, R0, R1, g, h); __syncthreads();   // L0 (7,6)
    gateP<5,4>(B64, A64, R0, R1, g, h); __syncthreads();   // L0 (5,4)
    gateP<3,2>(A64, B64, R0, R1, g, h); __syncthreads();   // L0 (3,2)
    gateP<1,0>(B64, A64, R0, R1, g, h); __syncthreads();   // L0 (1,0)
    loadPQ(PQv, 1, r0, R0, R1);
    gateP<7,5>(A64, B64, R0, R1, g, h); __syncthreads();   // L1 (7,5)
    gateP<3,1>(B64, A64, R0, R1, g, h); __syncthreads();   // L1 (3,1)
    gateP<5,3>(A64, B64, R0, R1, g, h); __syncthreads();   // L1 (5,3)
    gateP<1,0>(B64, A64, R0, R1, g, h); __syncthreads();   // L1 (1,0)  -> ends in bufA

    // ---- Exchange over DSMEM: peers' bufA -> own bufB ----
    CLUSTER_SYNC();
    {
        const unsigned bufA_a = sm32(bufA);
#pragma unroll
        for (int k = 0; k < 2; ++k) {
            unsigned l     = t + ((unsigned)k << 8);
            unsigned gi    = giB(bb, l);
            unsigned owner = gi >> 9;
            unsigned la    = gi & 511u;
            bufB[cswz(l)]  = dsld(bufA_a + cswz(la) * 8u, owner);
        }
    }
    __syncthreads();

    // ---- Phase B: local bits -> positions {0,1,5,7,8,9,10,11,12}.
    //      Ping-pong bufB <-> bufC only (bufA stays live for slow peers). ----
    loadPQ(PQv, 0, r0, R0, R1);
    gateP<8,7>(B64, C64, R0, R1, g, h); __syncthreads();   // L0 (12,11)
    gateP<6,5>(C64, B64, R0, R1, g, h); __syncthreads();   // L0 (10,9)
    gateP<7,6>(B64, C64, R0, R1, g, h); __syncthreads();   // L0 (11,10)
    gateP<5,4>(C64, B64, R0, R1, g, h); __syncthreads();   // L0 (9,8)
    loadPQ(PQv, 1, r0, R0, R1);
    gateP<7,5>(B64, C64, R0, R1, g, h); __syncthreads();   // L1 (11,9)
    gateP<5,3>(C64, B64, R0, R1, g, h); __syncthreads();   // L1 (9,7)
    loadPQ(PQv, 2, r0, R0, R1);
    gateP<5,2>(B64, C64, R0, R1, g, h); __syncthreads();   // L2 (9,5)
    gateP<1,0>(C64, B64, R0, R1, g, h); __syncthreads();   // L2 (1,0)
    gateP<2,1>(B64, C64, R0, R1, g, h); __syncthreads();   // L2 (5,1)
    gateP<0,5>(C64, B64, R0, R1, g, h); __syncthreads();   // L2 (0,9): high@pos0, low@pos9
    loadPQ(PQv, 3, r0, R0, R1);
    gateP<2,0>(B64, C64, R0, R1, g, h); __syncthreads();   // L3 (5,0) -> ends in bufC

    // ---- Readout partial: P(bit at position 0 == 0) over this chunk ----
    float ls = 0.f;
#pragma unroll
    for (int k = 0; k < 2; ++k) {
        unsigned l = t + ((unsigned)k << 8);
        if (!(l & 1u)) {
            c2 v = bufC[cswz(l)];
            ls = fmaf(v.x, v.x, fmaf(v.y, v.y, ls));
        }
    }
#pragma unroll
    for (int o = 16; o; o >>= 1) ls += __shfl_xor_sync(0xffffffffu, ls, o);
    if ((t & 31u) == 0u) red[t >> 5] = ls;
    __syncthreads();
    if (t == 0u) {
        float sp = 0.f;
#pragma unroll
        for (int w = 0; w < 8; ++w) sp += red[w];
        float2 p; p.x = n_part; p.y = sp;
        spart = p;
    }

    // ---- Final reduction over DSMEM (deterministic fixed order) ----
    CLUSTER_SYNC();
    if (rank == 0u && t == 0u) {
        const unsigned pa = sm32(&spart);
        float n = 0.f, s = 0.f;
#pragma unroll
        for (unsigned r = 0; r < CLUSTER; ++r) {
            c2 p = dsld(pa, r);
            n += p.x; s += p.y;
        }
        out[b] = s / n;
    }
    CLUSTER_SYNC();   // keep peers' smem alive until rank 0 finished reading
}

extern "C" void kernel_launch(void* const* d_in, const int* in_sizes, int n_in,
                              void* d_out, int out_size) {
    (void)in_sizes; (void)n_in; (void)out_size;
    const float* pr = (const float*)d_in[0];
    const float* pi = (const float*)d_in[1];
    const float* Hr = (const float*)d_in[2];
    const float* Hi = (const float*)d_in[3];
    float* out = (float*)d_out;

    cudaFuncSetAttribute(qcnn_kernel, cudaFuncAttributeNonPortableClusterSizeAllowed, 1);

    cudaLaunchConfig_t cfg = {};
    cfg.gridDim  = dim3(NBLK, 1, 1);
    cfg.blockDim = dim3(NT, 1, 1);
    cfg.dynamicSmemBytes = 0;
    cfg.stream = 0;
    cudaLaunchAttribute attr[1];
    attr[0].id = cudaLaunchAttributeClusterDimension;
    attr[0].val.clusterDim.x = CLUSTER;
    attr[0].val.clusterDim.y = 1;
    attr[0].val.clusterDim.z = 1;
    cfg.attrs = attr;
    cfg.numAttrs = 1;

    cudaLaunchKernelEx(&cfg, qcnn_kernel, pr, pi, Hr, Hi, out);
}

// round 5
// speedup vs baseline: 2.3642x; 1.0030x over previous
#include <cuda_runtime.h>
#include <cstdint>

// ---------------------------------------------------------------------------
// QCNN 13 qubits, B=2 -> 23 two-qubit gates. Grid 32 x 256, one 16-CTA
// cluster per batch. Amplitudes live in REGISTERS (2 per thread); all 23
// gates are warp-shuffle gates (no block barrier per gate). Layout remaps:
// two smem permutes (1 syncthreads each) + one DSMEM cluster exchange.
// ---------------------------------------------------------------------------

#define NT      256
#define NBLK    32
#define CLUSTER 16

typedef unsigned long long u64;

#define FMA2(d,a,b,c) asm("fma.rn.f32x2 %0,%1,%2,%3;" : "=l"(d) : "l"(a), "l"(b), "l"(c))
#define MUL2(d,a,b)   asm("mul.rn.f32x2 %0,%1,%2;"    : "=l"(d) : "l"(a), "l"(b))

__device__ __forceinline__ u64 swap64(u64 a) {
    unsigned lo, hi;
    asm("mov.b64 {%0,%1}, %2;" : "=r"(lo), "=r"(hi) : "l"(a));
    u64 r;
    asm("mov.b64 %0, {%1,%2};" : "=l"(r) : "r"(hi), "r"(lo));
    return r;
}
__device__ __forceinline__ u64 pack2(float x, float y) {
    u64 r; asm("mov.b64 %0, {%1,%2};" : "=l"(r) : "f"(x), "f"(y)); return r;
}
__device__ __forceinline__ float sq64(u64 v) {
    float x, y; asm("mov.b64 {%0,%1}, %2;" : "=f"(x), "=f"(y) : "l"(v));
    return fmaf(x, x, y * y);
}
__device__ __forceinline__ u64 shx64(u64 v, int m) {
    return __shfl_xor_sync(0xffffffffu, v, m);
}

// Remap fold: bits 4..8 of the 9-bit local index folded into bits 0..3.
__device__ __forceinline__ unsigned Ffold(unsigned h) {
    return (h & 15u) ^ ((h & 16u) ? 6u : 0u);
}
__device__ __forceinline__ unsigned swzR(unsigned l) {
    return l ^ Ffold((l >> 4) & 31u);
}

// Both gate bits in lane bits LP (high), LQ (low). V[r][x] = U[r][r^x],
// rows padded to 5 ulonglong2 (80B) -> conflict-free LDS.128.
template <int LP, int LQ, int L>
__device__ __forceinline__ void bothlane(u64& v0, u64& v1, unsigned lane,
                                         const ulonglong2* __restrict__ Vt) {
    unsigned r = (((lane >> LP) & 1u) << 1) | ((lane >> LQ) & 1u);
    const ulonglong2* row = Vt + L * 20 + (int)r * 5;
    ulonglong2 e0 = row[0], e1 = row[1], e2 = row[2], e3 = row[3];
    u64 b0 = shx64(v0, 1 << LQ), b1 = shx64(v1, 1 << LQ);
    u64 c0 = shx64(v0, 1 << LP), c1 = shx64(v1, 1 << LP);
    u64 d0 = shx64(v0, (1 << LP) | (1 << LQ)), d1 = shx64(v1, (1 << LP) | (1 << LQ));
    u64 t, s;
    MUL2(t, e0.x, v0); FMA2(t, e0.y, swap64(v0), t);
    FMA2(t, e1.x, b0, t); FMA2(t, e1.y, swap64(b0), t);
    FMA2(t, e2.x, c0, t); FMA2(t, e2.y, swap64(c0), t);
    FMA2(t, e3.x, d0, t); FMA2(t, e3.y, swap64(d0), t);
    MUL2(s, e0.x, v1); FMA2(s, e0.y, swap64(v1), s);
    FMA2(s, e1.x, b1, s); FMA2(s, e1.y, swap64(b1), s);
    FMA2(s, e2.x, c1, s); FMA2(s, e2.y, swap64(c1), s);
    FMA2(s, e3.x, d1, s); FMA2(s, e3.y, swap64(d1), s);
    v0 = t; v1 = s;
}

// High gate bit in lane bit LH, low gate bit = element bit (v0 <-> v1).
template <int LH, int L>
__device__ __forceinline__ void elemlane(u64& v0, u64& v1, unsigned lane,
                                         const ulonglong2* __restrict__ Vt) {
    unsigned bh = (lane >> LH) & 1u;
    const ulonglong2* r0p = Vt + L * 20 + (int)(bh << 1) * 5;
    const ulonglong2* r1p = r0p + 5;
    ulonglong2 a0 = r0p[0], a1 = r0p[1], a2 = r0p[2], a3 = r0p[3];
    ulonglong2 g0 = r1p[0], g1 = r1p[1], g2 = r1p[2], g3 = r1p[3];
    u64 w0 = shx64(v0, 1 << LH), w1 = shx64(v1, 1 << LH);
    u64 t, s;
    MUL2(t, a0.x, v0); FMA2(t, a0.y, swap64(v0), t);
    FMA2(t, a1.x, v1, t); FMA2(t, a1.y, swap64(v1), t);
    FMA2(t, a2.x, w0, t); FMA2(t, a2.y, swap64(w0), t);
    FMA2(t, a3.x, w1, t); FMA2(t, a3.y, swap64(w1), t);
    MUL2(s, g0.x, v1); FMA2(s, g0.y, swap64(v1), s);
    FMA2(s, g1.x, v0, s); FMA2(s, g1.y, swap64(v0), s);
    FMA2(s, g2.x, w1, s); FMA2(s, g2.y, swap64(w1), s);
    FMA2(s, g3.x, w0, s); FMA2(s, g3.y, swap64(w0), s);
    v0 = t; v1 = s;
}

__device__ __forceinline__ unsigned sm32(const void* p) {
    return (unsigned)__cvta_generic_to_shared(p);
}
__device__ __forceinline__ u64 dsld64(unsigned addr, unsigned rank) {
    unsigned ra;
    asm("mapa.shared::cluster.u32 %0, %1, %2;" : "=r"(ra) : "r"(addr), "r"(rank));
    u64 v;
    asm volatile("ld.shared::cluster.b64 %0, [%1];" : "=l"(v) : "r"(ra));
    return v;
}
__device__ __forceinline__ float2 dsldf2(unsigned addr, unsigned rank) {
    unsigned ra;
    asm("mapa.shared::cluster.u32 %0, %1, %2;" : "=r"(ra) : "r"(addr), "r"(rank));
    float x, y;
    asm volatile("ld.shared::cluster.v2.f32 {%0,%1}, [%2];" : "=f"(x), "=f"(y) : "r"(ra));
    return make_float2(x, y);
}
#define CLUSTER_SYNC() do { \
    asm volatile("barrier.cluster.arrive.aligned;" ::: "memory"); \
    asm volatile("barrier.cluster.wait.aligned;"   ::: "memory"); \
} while (0)

__global__ void __launch_bounds__(NT, 1)
qcnn_kernel(const float* __restrict__ pr, const float* __restrict__ pi,
            const float* __restrict__ Hr, const float* __restrict__ Hi,
            float* __restrict__ out)
{
    __shared__ u64 bufR[512];          // remap scratch (CTA-private)
    __shared__ u64 bufS[512];          // cluster exchange buffer
    __shared__ ulonglong2 Vt[80];      // V[L][r][x] = U[r][r^x], rows padded to 5
    __shared__ float2 red2[8];
    __shared__ float2 spart;

    const unsigned t    = threadIdx.x;
    const unsigned lane = t & 31u;
    const unsigned wq   = t >> 5;
    const unsigned b    = blockIdx.x >> 4;
    unsigned rank;
    asm("mov.u32 %0, %%cluster_ctarank;" : "=r"(rank));

    // ---- every thread loads its own 2 amps (map alpha: l = w | e<<3 | lane<<4,
    //      chunk bits = rank at positions 9..12) ----
    const float* prb = pr + (b << 13);
    const float* pib = pi + (b << 13);
    unsigned gi0 = (rank << 9) | wq | (lane << 4);
    u64 v0 = pack2(prb[gi0], pib[gi0]);
    u64 v1 = pack2(prb[gi0 | 8u], pib[gi0 | 8u]);
    float ns = sq64(v0) + sq64(v1);

    // ---- threads 0..63: shfl-based expm(H - H^dag), writes XOR-permuted V ----
    if (t < 64u) {
        const int L = (int)(t >> 4);
        const int e = (int)(t & 15u);
        const int i = e >> 2, j = e & 3;
        const unsigned seg = lane & 16u;
        const float* HrL = Hr + L * 16;
        const float* HiL = Hi + L * 16;
        float ar = HrL[e] - HrL[j * 4 + i];
        float ai = HiL[e] + HiL[j * 4 + i];
        float f2 = fmaf(ar, ar, ai * ai);
#pragma unroll
        for (int o = 8; o; o >>= 1) f2 += __shfl_xor_sync(0xffffffffu, f2, o);
        float fro = sqrtf(f2);
        int s = 0; float x = fro;
        while (x > 0.25f && s < 14) { x *= 0.5f; ++s; }
        float sc = ldexpf(1.f, -s);
        float Ar = ar * sc, Ai = ai * sc;
        float Tr = Ar, Ti = Ai;
        float Er = Ar + ((i == j) ? 1.f : 0.f), Ei = Ai;
#pragma unroll 1
        for (int k = 2; k <= 9; ++k) {
            float accr = 0.f, acci = 0.f;
#pragma unroll
            for (int m = 0; m < 4; ++m) {
                unsigned sT = seg | (unsigned)(i * 4 + m);
                unsigned sA = seg | (unsigned)(m * 4 + j);
                float tr = __shfl_sync(0xffffffffu, Tr, sT);
                float ti = __shfl_sync(0xffffffffu, Ti, sT);
                float br = __shfl_sync(0xffffffffu, Ar, sA);
                float bi = __shfl_sync(0xffffffffu, Ai, sA);
                accr = fmaf(tr, br, fmaf(-ti, bi, accr));
                acci = fmaf(tr, bi, fmaf( ti, br, acci));
            }
            float inv = 1.f / (float)k;
            Tr = accr * inv; Ti = acci * inv;
            Er += Tr; Ei += Ti;
        }
        int smax = s;
#pragma unroll
        for (int o = 16; o; o >>= 1) {
            int v = __shfl_xor_sync(0xffffffffu, smax, o);
            smax = v > smax ? v : smax;
        }
#pragma unroll 1
        for (int q = 0; q < smax; ++q) {
            float accr = 0.f, acci = 0.f;
#pragma unroll
            for (int m = 0; m < 4; ++m) {
                unsigned sR = seg | (unsigned)(i * 4 + m);
                unsigned sC = seg | (unsigned)(m * 4 + j);
                float rr = __shfl_sync(0xffffffffu, Er, sR);
                float ri = __shfl_sync(0xffffffffu, Ei, sR);
                float cr = __shfl_sync(0xffffffffu, Er, sC);
                float ci = __shfl_sync(0xffffffffu, Ei, sC);
                accr = fmaf(rr, cr, fmaf(-ri, ci, accr));
                acci = fmaf(rr, ci, fmaf( ri, cr, acci));
            }
            if (q < s) { Er = accr; Ei = acci; }
        }
        Vt[L * 20 + i * 5 + (i ^ j)] = make_ulonglong2(pack2(Er, Er), pack2(-Ei, Ei));
    }
    __syncthreads();

    // ---- Pass alpha (map: b3=e, b4..8=lane0..4, b0..2=w) ----
    bothlane<4,3,0>(v0, v1, lane, Vt);     // L0 (8,7)
    bothlane<2,1,0>(v0, v1, lane, Vt);     // L0 (6,5)
    elemlane<0,0>  (v0, v1, lane, Vt);     // L0 (4,3)
    bothlane<3,2,0>(v0, v1, lane, Vt);     // L0 (7,6)
    bothlane<1,0,0>(v0, v1, lane, Vt);     // L0 (5,4)
    bothlane<3,1,1>(v0, v1, lane, Vt);     // L1 (7,5)

    // ---- Remap alpha -> beta (b0..3=lane0..3, b4=e, b5=lane4, b6..8=w) ----
    {
        unsigned la0 = wq | (lane << 4);
        bufR[swzR(la0)]      = v0;
        bufR[swzR(la0 | 8u)] = v1;
        __syncthreads();
        unsigned lb0 = (lane & 15u) | (((lane >> 4) & 1u) << 5) | (wq << 6);
        v0 = bufR[swzR(lb0)];
        v1 = bufR[swzR(lb0 | 16u)];
    }

    // ---- Pass beta ----
    bothlane<2,1,0>(v0, v1, lane, Vt);     // L0 (2,1)
    bothlane<3,2,0>(v0, v1, lane, Vt);     // L0 (3,2)
    bothlane<1,0,0>(v0, v1, lane, Vt);     // L0 (1,0)
    bothlane<3,1,1>(v0, v1, lane, Vt);     // L1 (3,1)
    bothlane<4,3,1>(v0, v1, lane, Vt);     // L1 (5,3)
    bothlane<1,0,1>(v0, v1, lane, Vt);     // L1 (1,0)

    // ---- Cluster exchange: store (identity on local-A index), sync, DSMEM read
    {
        unsigned lb0 = (lane & 15u) | (((lane >> 4) & 1u) << 5) | (wq << 6);
        bufS[lb0]       = v0;
        bufS[lb0 | 16u] = v1;
        CLUSTER_SYNC();
        const unsigned base = sm32(bufS);
        unsigned owner = (lane >> 1) & 15u;
        unsigned lac = (wq & 3u) | ((rank & 7u) << 2) | (((wq >> 2) & 1u) << 5)
                     | (((rank >> 3) & 1u) << 6) | ((lane & 1u) << 8);
        v0 = dsld64(base + (lac      ) * 8u, owner);   // e=0 (position 7 bit = 0)
        v1 = dsld64(base + (lac | 128u) * 8u, owner);  // e=1
    }

    // ---- Pass gamma (local-B; same slot map as alpha) ----
    bothlane<4,3,0>(v0, v1, lane, Vt);     // L0 (12,11)
    bothlane<2,1,0>(v0, v1, lane, Vt);     // L0 (10,9)
    bothlane<3,2,0>(v0, v1, lane, Vt);     // L0 (11,10)
    bothlane<1,0,0>(v0, v1, lane, Vt);     // L0 (9,8)
    bothlane<3,1,1>(v0, v1, lane, Vt);     // L1 (11,9)
    elemlane<1,1>  (v0, v1, lane, Vt);     // L1 (9,7): high=pos9(lane1), low=pos7(elem)

    // ---- Remap gamma -> delta (same slot permutation as alpha -> beta) ----
    {
        unsigned la0 = wq | (lane << 4);
        bufR[swzR(la0)]      = v0;
        bufR[swzR(la0 | 8u)] = v1;
        __syncthreads();
        unsigned lb0 = (lane & 15u) | (((lane >> 4) & 1u) << 5) | (wq << 6);
        v0 = bufR[swzR(lb0)];
        v1 = bufR[swzR(lb0 | 16u)];
    }

    // ---- Pass delta ----
    bothlane<4,2,2>(v0, v1, lane, Vt);     // L2 (9,5)
    bothlane<1,0,2>(v0, v1, lane, Vt);     // L2 (1,0)
    bothlane<2,1,2>(v0, v1, lane, Vt);     // L2 (5,1)
    bothlane<0,4,2>(v0, v1, lane, Vt);     // L2 (0,9): high=pos0(lane0), low=pos9(lane4)
    bothlane<2,0,3>(v0, v1, lane, Vt);     // L3 (5,0)

    // ---- Readout: P(position 0 == 0); position 0 = delta lane bit 0 ----
    float ls = (lane & 1u) ? 0.f : (sq64(v0) + sq64(v1));
#pragma unroll
    for (int o = 16; o; o >>= 1) {
        ns += __shfl_xor_sync(0xffffffffu, ns, o);
        ls += __shfl_xor_sync(0xffffffffu, ls, o);
    }
    if (lane == 0u) red2[wq] = make_float2(ns, ls);
    __syncthreads();
    if (t == 0u) {
        float n = 0.f, s = 0.f;
#pragma unroll
        for (int w = 0; w < 8; ++w) { n += red2[w].x; s += red2[w].y; }
        spart = make_float2(n, s);
    }

    CLUSTER_SYNC();
    if (rank == 0u && t == 0u) {
        const unsigned pa = sm32(&spart);
        float n = 0.f, s = 0.f;
#pragma unroll
        for (unsigned r = 0; r < CLUSTER; ++r) {
            float2 p = dsldf2(pa, r);
            n += p.x; s += p.y;
        }
        out[b] = s / n;
    }
    CLUSTER_SYNC();   // keep peers' smem alive until rank 0 finished reading
}

extern "C" void kernel_launch(void* const* d_in, const int* in_sizes, int n_in,
                              void* d_out, int out_size) {
    (void)in_sizes; (void)n_in; (void)out_size;
    const float* pr = (const float*)d_in[0];
    const float* pi = (const float*)d_in[1];
    const float* Hr = (const float*)d_in[2];
    const float* Hi = (const float*)d_in[3];
    float* out = (float*)d_out;

    cudaFuncSetAttribute(qcnn_kernel, cudaFuncAttributeNonPortableClusterSizeAllowed, 1);

    cudaLaunchConfig_t cfg = {};
    cfg.gridDim  = dim3(NBLK, 1, 1);
    cfg.blockDim = dim3(NT, 1, 1);
    cfg.dynamicSmemBytes = 0;
    cfg.stream = 0;
    cudaLaunchAttribute attr[1];
    attr[0].id = cudaLaunchAttributeClusterDimension;
    attr[0].val.clusterDim.x = CLUSTER;
    attr[0].val.clusterDim.y = 1;
    attr[0].val.clusterDim.z = 1;
    cfg.attrs = attr;
    cfg.numAttrs = 1;

    cudaLaunchKernelEx(&cfg, qcnn_kernel, pr, pi, Hr, Hi, out);
}